// round 15
// baseline (speedup 1.0000x reference)
#include <cuda_runtime.h>
#include <cuda_fp16.h>
#include <math.h>
#include <stdint.h>

// ---------------- problem constants ----------------
#define BV   32000
#define TT   2048
#define HH   4
#define NN_  4096
#define DD   256
#define LL   6
#define KK   1024
#define BB   2
#define EPS  1e-5f

// ---------------- device scratch (no mallocs allowed) ----------------
__device__ float  g_v   [4096L*256];
__device__ __half g_v2a [4096L*256];     // [B*T, D] hi
__device__ __half g_vT  [2L*256*2048];   // [B][D, T] hi (written by embed/combine)
__device__ __half g_x   [8L*2048*1024];  // [B,H,T,K] fp16 gate (PERMUTED cols)
__device__ __half g_qh  [8L*2048*1024];  // [B,H,T,K] q hi (PERMUTED cols)
__device__ __half g_qT  [8L*1024*2048];  // [B,H,K,T] q^T hi
__device__ __half g_wT  [8L*256*1024];   // [B,H,D,K] w^T hi, w = q^T v
__device__ float  g_a   [8L*2048*256];
__device__ __half g_a2  [8L*2048*256];   // hi
__device__ __half g_y2  [2L*2048*4096];  // [B,T,N] hi (PERMUTED cols/head)
__device__ float  g_yE  [4L*4096*256];   // 4 split-K partials
__device__ __half g_Dx2 [4L*1024*256];   // [H][K, D] hi (PERMUTED rows)
__device__ __half g_Dy2 [4L*1024*256];
__device__ __half g_E2  [256L*4096];     // [D, N] hi (PERMUTED cols/head)
__device__ __half g_ro2 [32000L*256];    // [V, D] hi
__device__ float  g_cos [2048L*512];     // [T, 512]
__device__ float  g_sin [2048L*512];

// per-head column permutation: k<512 -> 2k ; k>=512 -> 2k-1023
__host__ __device__ __forceinline__ int permk(int k) {
    return (k < 512) ? (2 * k) : (2 * k - 1023);
}

// ---------------- PTX helpers (baseline ISA only: sm_80-class) ----------------
__device__ __forceinline__ uint32_t smem_u32(const void* p) {
    uint32_t a;
    asm("{ .reg .u64 t; cvta.to.shared.u64 t, %1; cvt.u32.u64 %0, t; }" : "=r"(a) : "l"(p));
    return a;
}
#define CP_ASYNC16(saddr, gaddr) \
    asm volatile("cp.async.cg.shared.global [%0], [%1], 16;" :: "r"(saddr), "l"(gaddr))
#define CP_COMMIT() asm volatile("cp.async.commit_group;" ::: "memory")
#define CP_WAIT1()  asm volatile("cp.async.wait_group 1;" ::: "memory")

#define LDSM_X4(r0, r1, r2, r3, addr) \
    asm volatile("ldmatrix.sync.aligned.m8n8.x4.shared.b16 {%0,%1,%2,%3}, [%4];" \
        : "=r"(r0), "=r"(r1), "=r"(r2), "=r"(r3) : "r"(addr))

#define MMA16816(d, a, b0, b1) \
    asm volatile("mma.sync.aligned.m16n8k16.row.col.f32.f16.f16.f32 " \
        "{%0,%1,%2,%3}, {%4,%5,%6,%7}, {%8,%9}, {%0,%1,%2,%3};" \
        : "+f"((d)[0]), "+f"((d)[1]), "+f"((d)[2]), "+f"((d)[3]) \
        : "r"((a)[0]), "r"((a)[1]), "r"((a)[2]), "r"((a)[3]), "r"(b0), "r"(b1))

__device__ __forceinline__ uint32_t pack2(__half a, __half b) {
    return (uint32_t)__half_as_ushort(a) | ((uint32_t)__half_as_ushort(b) << 16);
}

// swizzled smem offset: 64B rows, seg' = seg ^ ((row>>1)&3)
__device__ __forceinline__ uint32_t swz(uint32_t row, uint32_t seg) {
    return row * 64u + (((seg) ^ ((row >> 1) & 3u)) << 4);
}

// ---------------- block reduction (256 threads) ----------------
__device__ __forceinline__ float blockReduceSum256(float val) {
    __shared__ float s[8];
    __shared__ float res;
    int lane = threadIdx.x & 31, w = threadIdx.x >> 5;
    #pragma unroll
    for (int o = 16; o; o >>= 1) val += __shfl_xor_sync(0xffffffffu, val, o);
    if (lane == 0) s[w] = val;
    __syncthreads();
    if (threadIdx.x < 8) {
        float v = s[threadIdx.x];
        #pragma unroll
        for (int o = 4; o; o >>= 1) v += __shfl_xor_sync(0xffu, v, o);
        if (threadIdx.x == 0) res = v;
    }
    __syncthreads();
    float r = res;
    __syncthreads();
    return r;
}

// ---------------- elementwise kernels ----------------
__global__ void rope_table_kernel() {
    long idx = (long)blockIdx.x * blockDim.x + threadIdx.x;
    if (idx >= (long)TT * 512) return;
    int t = (int)(idx >> 9);
    int i = (int)(idx & 511);
    float ex  = (2.0f * (float)i) / (float)KK;
    float inv = 1.0f / powf(10000.0f, ex);
    float th  = (float)t * inv;
    g_cos[idx] = cosf(th);
    g_sin[idx] = sinf(th);
}

// v = ln(emb[input]) + pos; writes v fp32, v2a fp16, and vT fp16 (scatter)
__global__ void embed_ln_kernel(const int* __restrict__ input_,
                                const float* __restrict__ emb,
                                const float* __restrict__ pos) {
    int row = blockIdx.x;                 // B*T
    int t = row & (TT - 1);
    int b = row >> 11;
    int tok = input_[row];
    float x = emb[(long)tok * DD + threadIdx.x];
    float mu = blockReduceSum256(x) * (1.0f / DD);
    float d = x - mu;
    float var = blockReduceSum256(d * d) * (1.0f / DD);
    float f = d * rsqrtf(var + EPS) + pos[(long)t * DD + threadIdx.x];
    g_v[(long)row * DD + threadIdx.x] = f;
    __half h = __float2half_rn(f);
    g_v2a[(long)row * DD + threadIdx.x] = h;
    g_vT[(long)b * DD * TT + (long)threadIdx.x * TT + t] = h;
}

// v = ln(v + ln(sum of 4 yE partials)) [+ pos]; writes v, v2a, vT
__global__ void combine_split_kernel(const float* __restrict__ pos, int do_pos) {
    long row = blockIdx.x;                 // B*T
    int t = (int)(row & (TT - 1));
    int b = (int)(row >> 11);
    const long P = 4096L * 256;
    float u = g_yE[row * DD + threadIdx.x] + g_yE[P + row * DD + threadIdx.x] +
              g_yE[2 * P + row * DD + threadIdx.x] + g_yE[3 * P + row * DD + threadIdx.x];
    float mu = blockReduceSum256(u) * (1.0f / DD);
    float d = u - mu;
    float var = blockReduceSum256(d * d) * (1.0f / DD);
    float w = g_v[row * DD + threadIdx.x] + d * rsqrtf(var + EPS);
    float mu2 = blockReduceSum256(w) * (1.0f / DD);
    float d2 = w - mu2;
    float var2 = blockReduceSum256(d2 * d2) * (1.0f / DD);
    float f = d2 * rsqrtf(var2 + EPS);
    if (do_pos) f += pos[(long)t * DD + threadIdx.x];
    g_v[row * DD + threadIdx.x] = f;
    __half h = __float2half_rn(f);
    g_v2a[row * DD + threadIdx.x] = h;
    g_vT[(long)b * DD * TT + (long)threadIdx.x * TT + t] = h;
}

__global__ void ln_split_kernel() {
    long row = blockIdx.x;                 // B*H*T
    float x = g_a[row * DD + threadIdx.x];
    float mu = blockReduceSum256(x) * (1.0f / DD);
    float d = x - mu;
    float var = blockReduceSum256(d * d) * (1.0f / DD);
    float f = d * rsqrtf(var + EPS);
    g_a2[row * DD + threadIdx.x] = __float2half_rn(f);
}

// X [R,C] fp32 -> Y [C, R] fp16 hi (weight prep only)
// PERM: 0 = none; 1 = permute OUT-ROW (X column) per 1024-block;
//       2 = permute OUT-COL (X row) per 1024-block.
__global__ void transpose_half_kernel(const float* __restrict__ X,
                                      __half* __restrict__ Y,
                                      int R, int C, long inZ, long outZ, int PERM) {
    __shared__ float tile[32][33];
    X += (long)blockIdx.z * inZ;
    Y += (long)blockIdx.z * outZ;
    int r0 = blockIdx.y * 32, c0 = blockIdx.x * 32;
    int tx = threadIdx.x, ty = threadIdx.y;   // (32,8)
    #pragma unroll
    for (int i = 0; i < 32; i += 8)
        tile[ty + i][tx] = X[(long)(r0 + ty + i) * C + c0 + tx];
    __syncthreads();
    #pragma unroll
    for (int i = 0; i < 32; i += 8) {
        float f = tile[tx][ty + i];           // X[r0+tx][c0+ty+i]
        int orowi = c0 + ty + i;
        int ocol  = r0 + tx;
        if (PERM == 1) {
            int blk = orowi & ~1023;
            orowi = blk + permk(orowi & 1023);
        } else if (PERM == 2) {
            int blk = ocol & ~1023;
            ocol = blk + permk(ocol & 1023);
        }
        Y[(long)orowi * R + ocol] = __float2half_rn(f);
    }
}

// ---------------- mma.sync GEMM (HMMA fp16 single-pass hi x hi) ----------------
// C[M,N] = Ah[M,K] x Bh[N,K]^T, fp32 accum.
// CTA tile 128x128, 3-stage cp.async pipeline (stage = 2 x 8192B = 16KB),
// XOR-swizzled 64B smem rows, single __syncthreads per chunk.
// 8 warps 2(m) x 4(n), warp tile 64x32.
// EPI: 0=fp32, 1=fp16 hi, 3=relu*G(fp16) -> fp16 hi,
//      4=relu + fused RoPE -> x gate fp16 [t,k] + qh [t,k] + qT [k,t]
// Split-K: nsplit partials, sp = blockIdx.z % nsplit.
#define OPER_BYTES 8192                    // 128 rows x 64B
#define STAGE_BYTES (2 * OPER_BYTES)       // 16384: Ah|Bh
#define SMEM_GEMM_BYTES (3 * STAGE_BYTES)  // 49152

template<int EPI>
__global__ void __launch_bounds__(256, 2)
gemm_mma(const __half* __restrict__ A, const __half* __restrict__ B,
         void* __restrict__ Cv, const __half* __restrict__ G,
         int Kd, int lda, int ldb, int ldc, int ldgt,
         long sAb, long sAh, long sBb, long sBh, long sCb, long sCh,
         long sGb, long sGh, int Hdim, int nsplit, long sSplitC,
         __half* __restrict__ Qh, __half* __restrict__ QT,
         const float* __restrict__ CT, const float* __restrict__ ST)
{
    extern __shared__ char dsm[];
    uint32_t sbase = smem_u32(dsm);

    int tid = threadIdx.x;
    int lane = tid & 31;
    int wid = tid >> 5;
    int wm = wid >> 2;        // 0..1
    int wn = wid & 3;         // 0..3

    int zz = blockIdx.z;
    int sp = 0, z = zz;
    if (nsplit > 1) { sp = zz % nsplit; z = zz / nsplit; }
    int bb = z / Hdim, hh = z - bb * Hdim;
    A += bb * sAb + hh * sAh;
    B += bb * sBb + hh * sBh;
    long cOff = bb * sCb + hh * sCh + sp * sSplitC;
    if (EPI == 3) G += bb * sGb + hh * sGh;
    long qhOff = 0, qtOff = 0;
    if (EPI == 4) {
        qhOff = (long)z * ((long)TT * KK);
        qtOff = (long)z * ((long)KK * TT);
    }

    int m0 = blockIdx.y * 128;
    int n0 = blockIdx.x * 128;

    const int KC = Kd >> 5;       // 32-wide chunks
    const int spK = sp * Kd;

    int lrow = tid >> 2;          // 0..63
    int lseg = tid & 3;

    auto issue = [&](int cc) {
        int koff = spK + (cc << 5);
        uint32_t st = sbase + (cc % 3) * STAGE_BYTES;
        #pragma unroll
        for (int i = 0; i < 2; i++) {
            uint32_t row = lrow + i * 64;
            uint32_t so = swz(row, (uint32_t)lseg);
            long go = lseg * 8;
            const __half* ga = A + (long)(m0 + row) * lda + koff + go;
            const __half* gb = B + (long)(n0 + row) * ldb + koff + go;
            CP_ASYNC16(st + so,              ga);
            CP_ASYNC16(st + OPER_BYTES + so, gb);
        }
    };

    float acc[4][4][4];
    #pragma unroll
    for (int i = 0; i < 4; i++)
        #pragma unroll
        for (int j = 0; j < 4; j++)
            #pragma unroll
            for (int r = 0; r < 4; r++) acc[i][j][r] = 0.0f;

    issue(0); CP_COMMIT();
    issue(1); CP_COMMIT();

    int rsel = lane & 15;
    int hi16 = lane >> 4;         // 0 or 1: second 16B seg of the k16 block

    for (int c = 0; c < KC; c++) {
        CP_WAIT1();              // chunk c data complete
        __syncthreads();         // copies visible; compute c-1 done

        uint32_t sah = sbase + (c % 3) * STAGE_BYTES;
        uint32_t sbh = sah + OPER_BYTES;

        #pragma unroll
        for (int ks = 0; ks < 2; ks++) {
            uint32_t segb = (uint32_t)(ks * 2 + hi16);
            uint32_t ar[4][4], br[2][4];
            #pragma unroll
            for (int n2 = 0; n2 < 2; n2++) {
                uint32_t row = (uint32_t)(wn * 32 + n2 * 16 + rsel);
                LDSM_X4(br[n2][0], br[n2][1], br[n2][2], br[n2][3], sbh + swz(row, segb));
            }
            #pragma unroll
            for (int mt = 0; mt < 4; mt++) {
                uint32_t row = (uint32_t)(wm * 64 + mt * 16 + rsel);
                LDSM_X4(ar[mt][0], ar[mt][1], ar[mt][2], ar[mt][3], sah + swz(row, segb));
            }
            #pragma unroll
            for (int mt = 0; mt < 4; mt++)
                #pragma unroll
                for (int nt = 0; nt < 4; nt++) {
                    int n2 = nt >> 1, j = nt & 1;
                    MMA16816(acc[mt][nt], ar[mt], br[n2][j], br[n2][2 + j]);
                }
            // hide next-chunk copy issue under the tensor-pipe shadow
            if (ks == 0) {
                if (c + 2 < KC) issue(c + 2);
                CP_COMMIT();
            }
        }
    }

    // ---------------- epilogue ----------------
    int g = lane >> 2, tg = lane & 3;
    float* Cf = (float*)Cv;
    __half* Cb = (__half*)Cv;

    #pragma unroll
    for (int mt = 0; mt < 4; mt++) {
        #pragma unroll
        for (int half = 0; half < 2; half++) {
            long row = m0 + wm * 64 + mt * 16 + g + half * 8;
            #pragma unroll
            for (int nt = 0; nt < 4; nt++) {
                int co = n0 + wn * 32 + nt * 8 + tg * 2;
                float f0 = acc[mt][nt][half * 2 + 0];
                float f1 = acc[mt][nt][half * 2 + 1];
                if (EPI == 0) {
                    *reinterpret_cast<float2*>(&Cf[cOff + row * ldc + co]) =
                        make_float2(f0, f1);
                } else if (EPI == 1) {
                    *reinterpret_cast<uint32_t*>(&Cb[cOff + row * ldc + co]) =
                        pack2(__float2half_rn(f0), __float2half_rn(f1));
                } else if (EPI == 4) {
                    f0 = fmaxf(f0, 0.f);
                    f1 = fmaxf(f1, 0.f);
                    // gate x in fp16 (permuted cols)
                    *reinterpret_cast<uint32_t*>(&Cb[cOff + row * ldc + co]) =
                        pack2(__float2half_rn(f0), __float2half_rn(f1));
                    // RoPE: pair (co, co+1) = original (i, i+512), i = co/2
                    int i = co >> 1;
                    long tb = row * 512 + i;   // row == t
                    float cv = CT[tb], sv = ST[tb];
                    float qa = f0 * cv - f1 * sv;
                    float qb = f1 * cv + f0 * sv;
                    __half h0 = __float2half_rn(qa);
                    __half h1 = __float2half_rn(qb);
                    *reinterpret_cast<uint32_t*>(&Qh[qhOff + row * KK + co]) = pack2(h0, h1);
                    __half* qt = QT + qtOff + (long)co * TT + row;
                    qt[0]  = h0;
                    qt[TT] = h1;
                } else {  // EPI == 3
                    __half2 gv = *reinterpret_cast<const __half2*>(
                        &G[row * (long)ldgt + co]);
                    f0 = fmaxf(f0, 0.f) * __half2float(__low2half(gv));
                    f1 = fmaxf(f1, 0.f) * __half2float(__high2half(gv));
                    *reinterpret_cast<uint32_t*>(&Cb[cOff + row * ldc + co]) =
                        pack2(__float2half_rn(f0), __float2half_rn(f1));
                }
            }
        }
    }
}

// ---------------- host launch ----------------
extern "C" void kernel_launch(void* const* d_in, const int* in_sizes, int n_in,
                              void* d_out, int out_size) {
    const int*   input_  = (const int*)d_in[0];
    const float* emb     = (const float*)d_in[1];
    const float* pos     = (const float*)d_in[2];
    const float* Dx      = (const float*)d_in[3];
    const float* Dy      = (const float*)d_in[4];
    const float* E       = (const float*)d_in[5];
    const float* readout = (const float*)d_in[6];
    float* out = (float*)d_out;

    cudaFuncSetAttribute(gemm_mma<0>, cudaFuncAttributeMaxDynamicSharedMemorySize, SMEM_GEMM_BYTES);
    cudaFuncSetAttribute(gemm_mma<1>, cudaFuncAttributeMaxDynamicSharedMemorySize, SMEM_GEMM_BYTES);
    cudaFuncSetAttribute(gemm_mma<3>, cudaFuncAttributeMaxDynamicSharedMemorySize, SMEM_GEMM_BYTES);
    cudaFuncSetAttribute(gemm_mma<4>, cudaFuncAttributeMaxDynamicSharedMemorySize, SMEM_GEMM_BYTES);

    float *v, *a, *yE, *ct, *st;
    __half *v2a, *vT, *x, *qh, *qT, *wT, *a2, *y2, *Dx2, *Dy2, *E2, *ro2;
    cudaGetSymbolAddress((void**)&v,   g_v);
    cudaGetSymbolAddress((void**)&v2a, g_v2a);
    cudaGetSymbolAddress((void**)&vT,  g_vT);
    cudaGetSymbolAddress((void**)&x,   g_x);
    cudaGetSymbolAddress((void**)&qh,  g_qh);
    cudaGetSymbolAddress((void**)&qT,  g_qT);
    cudaGetSymbolAddress((void**)&wT,  g_wT);
    cudaGetSymbolAddress((void**)&a,   g_a);
    cudaGetSymbolAddress((void**)&a2,  g_a2);
    cudaGetSymbolAddress((void**)&y2,  g_y2);
    cudaGetSymbolAddress((void**)&yE,  g_yE);
    cudaGetSymbolAddress((void**)&Dx2, g_Dx2);
    cudaGetSymbolAddress((void**)&Dy2, g_Dy2);
    cudaGetSymbolAddress((void**)&E2,  g_E2);
    cudaGetSymbolAddress((void**)&ro2, g_ro2);
    cudaGetSymbolAddress((void**)&ct,  g_cos);
    cudaGetSymbolAddress((void**)&st,  g_sin);

    dim3 tb(32, 8);

    rope_table_kernel<<<(TT * 512 + 255) / 256, 256>>>();
    embed_ln_kernel<<<BB * TT, 256>>>(input_, emb, pos);
    transpose_half_kernel<<<dim3(KK / 32, DD / 32, HH), tb>>>(Dx, Dx2, DD, KK, (long)DD * KK, (long)KK * DD, 1);
    transpose_half_kernel<<<dim3(KK / 32, DD / 32, HH), tb>>>(Dy, Dy2, DD, KK, (long)DD * KK, (long)KK * DD, 1);
    transpose_half_kernel<<<dim3(DD / 32, NN_ / 32, 1), tb>>>(E, E2, NN_, DD, 0, 0, 2);
    transpose_half_kernel<<<dim3(BV / 32, DD / 32, 1), tb>>>(readout, ro2, DD, BV, 0, 0, 0);

    const long TK  = (long)TT * KK;
    const long TD  = (long)TT * DD;
    const long TN  = (long)TT * NN_;
    const long QTS = (long)KK * TT;        // qT per-bh stride
    const long WTS = (long)DD * KK;        // wT per-bh stride

    for (int l = 0; l < LL; l++) {
        // x = relu(v2a @ Dx2^T) fp16 gate (permuted) + RoPE -> qh [t,k], qT [k,t]
        gemm_mma<4><<<dim3(KK / 128, TT / 128, BB * HH), 256, SMEM_GEMM_BYTES>>>(
            v2a, Dx2, x, nullptr,
            DD, DD, DD, KK, 0,
            TD, 0, 0, (long)KK * DD, (long)HH * TK, TK, 0, 0, HH, 1, 0,
            qh, qT, ct, st);

        // wT[b,h] = vT @ qT^T (fp16 hi) : M=256(d) N=1024(k) Kc=2048(t)
        gemm_mma<1><<<dim3(KK / 128, DD / 128, BB * HH), 256, SMEM_GEMM_BYTES>>>(
            vT, qT, wT, nullptr,
            TT, TT, TT, KK, 0,
            (long)DD * TT, 0, (long)HH * QTS, QTS, (long)HH * WTS, WTS, 0, 0, HH, 1, 0,
            nullptr, nullptr, nullptr, nullptr);

        // a[b,h] = qh @ wT^T fp32 : M=2048(t) N=256(d) Kc=1024(k)
        gemm_mma<0><<<dim3(DD / 128, TT / 128, BB * HH), 256, SMEM_GEMM_BYTES>>>(
            qh, wT, a, nullptr,
            KK, KK, KK, DD, 0,
            (long)HH * TK, TK, (long)HH * WTS, WTS, (long)HH * TD, TD, 0, 0, HH, 1, 0,
            nullptr, nullptr, nullptr, nullptr);

        ln_split_kernel<<<BB * HH * TT, 256>>>();

        // y2[b,t,h*K+n'] = relu(a2 @ Dy2^T) * x (fp16, permuted cols)
        gemm_mma<3><<<dim3(KK / 128, TT / 128, BB * HH), 256, SMEM_GEMM_BYTES>>>(
            a2, Dy2, y2, x,
            DD, DD, DD, NN_, KK,
            (long)HH * TD, TD, 0, (long)KK * DD,
            TN, (long)KK, (long)HH * TK, TK, HH, 1, 0,
            nullptr, nullptr, nullptr, nullptr);

        // yE partials = y2 @ E2^T (split-K=4) : M=4096 N=256
        gemm_mma<0><<<dim3(DD / 128, (BB * TT) / 128, 4), 256, SMEM_GEMM_BYTES>>>(
            y2, E2, yE, nullptr,
            NN_ / 4, NN_, NN_, DD, 0,
            0, 0, 0, 0, 0, 0, 0, 0, 1, 4, 4096L * 256,
            nullptr, nullptr, nullptr, nullptr);

        combine_split_kernel<<<BB * TT, 256>>>(pos, l < LL - 1 ? 1 : 0);
    }

    // out = v2a @ ro2^T fp32 : M=4096 N=32000 Kd=256
    gemm_mma<0><<<dim3(BV / 128, (BB * TT) / 128, 1), 256, SMEM_GEMM_BYTES>>>(
        v2a, ro2, out, nullptr,
        DD, DD, DD, BV, 0,
        0, 0, 0, 0, 0, 0, 0, 0, 1, 1, 0,
        nullptr, nullptr, nullptr, nullptr);
}

// round 16
// speedup vs baseline: 1.0247x; 1.0247x over previous
#include <cuda_runtime.h>
#include <cuda_fp16.h>
#include <math.h>
#include <stdint.h>

// ---------------- problem constants ----------------
#define BV   32000
#define TT   2048
#define HH   4
#define NN_  4096
#define DD   256
#define LL   6
#define KK   1024
#define BB   2
#define EPS  1e-5f

// ---------------- device scratch (no mallocs allowed) ----------------
__device__ float  g_v   [4096L*256];
__device__ __half g_v2a [4096L*256];     // [B*T, D] hi
__device__ __half g_vT  [2L*256*2048];   // [B][D, T] hi
__device__ __half g_x   [8L*2048*1024];  // [B,H,T,K] fp16 gate (PERMUTED cols)
__device__ __half g_qh  [8L*2048*1024];  // [B,H,T,K] q hi (PERMUTED cols)
__device__ __half g_qT  [8L*1024*2048];  // [B,H,K,T] q^T hi
__device__ float  g_wP  [2L*8*256*1024]; // wGEMM split-K partials (fp32)
__device__ __half g_wT  [8L*256*1024];   // [B,H,D,K] w^T hi, w = q^T v
__device__ float  g_a   [8L*2048*256];
__device__ __half g_a2  [8L*2048*256];   // hi
__device__ __half g_y2  [2L*2048*4096];  // [B,T,N] hi (PERMUTED cols/head)
__device__ float  g_yE  [4L*4096*256];   // 4 split-K partials
__device__ __half g_Dx2 [4L*1024*256];   // [H][K, D] hi (PERMUTED rows)
__device__ __half g_Dy2 [4L*1024*256];
__device__ __half g_E2  [256L*4096];     // [D, N] hi (PERMUTED cols/head)
__device__ __half g_ro2 [32000L*256];    // [V, D] hi
__device__ float  g_cos [2048L*512];     // [T, 512]
__device__ float  g_sin [2048L*512];

// per-head column permutation: k<512 -> 2k ; k>=512 -> 2k-1023
__host__ __device__ __forceinline__ int permk(int k) {
    return (k < 512) ? (2 * k) : (2 * k - 1023);
}

// ---------------- PTX helpers (baseline ISA only: sm_80-class) ----------------
__device__ __forceinline__ uint32_t smem_u32(const void* p) {
    uint32_t a;
    asm("{ .reg .u64 t; cvta.to.shared.u64 t, %1; cvt.u32.u64 %0, t; }" : "=r"(a) : "l"(p));
    return a;
}
#define CP_ASYNC16(saddr, gaddr) \
    asm volatile("cp.async.cg.shared.global [%0], [%1], 16;" :: "r"(saddr), "l"(gaddr))
#define CP_COMMIT() asm volatile("cp.async.commit_group;" ::: "memory")
#define CP_WAIT1()  asm volatile("cp.async.wait_group 1;" ::: "memory")

#define LDSM_X4(r0, r1, r2, r3, addr) \
    asm volatile("ldmatrix.sync.aligned.m8n8.x4.shared.b16 {%0,%1,%2,%3}, [%4];" \
        : "=r"(r0), "=r"(r1), "=r"(r2), "=r"(r3) : "r"(addr))

#define MMA16816(d, a, b0, b1) \
    asm volatile("mma.sync.aligned.m16n8k16.row.col.f32.f16.f16.f32 " \
        "{%0,%1,%2,%3}, {%4,%5,%6,%7}, {%8,%9}, {%0,%1,%2,%3};" \
        : "+f"((d)[0]), "+f"((d)[1]), "+f"((d)[2]), "+f"((d)[3]) \
        : "r"((a)[0]), "r"((a)[1]), "r"((a)[2]), "r"((a)[3]), "r"(b0), "r"(b1))

__device__ __forceinline__ uint32_t pack2(__half a, __half b) {
    return (uint32_t)__half_as_ushort(a) | ((uint32_t)__half_as_ushort(b) << 16);
}

// swizzled smem offset: 64B rows, seg' = seg ^ ((row>>1)&3)
__device__ __forceinline__ uint32_t swz(uint32_t row, uint32_t seg) {
    return row * 64u + (((seg) ^ ((row >> 1) & 3u)) << 4);
}

// ---------------- block reduction (256 threads) ----------------
__device__ __forceinline__ float blockReduceSum256(float val) {
    __shared__ float s[8];
    __shared__ float res;
    int lane = threadIdx.x & 31, w = threadIdx.x >> 5;
    #pragma unroll
    for (int o = 16; o; o >>= 1) val += __shfl_xor_sync(0xffffffffu, val, o);
    if (lane == 0) s[w] = val;
    __syncthreads();
    if (threadIdx.x < 8) {
        float v = s[threadIdx.x];
        #pragma unroll
        for (int o = 4; o; o >>= 1) v += __shfl_xor_sync(0xffu, v, o);
        if (threadIdx.x == 0) res = v;
    }
    __syncthreads();
    float r = res;
    __syncthreads();
    return r;
}

// ---------------- elementwise kernels ----------------
__global__ void rope_table_kernel() {
    long idx = (long)blockIdx.x * blockDim.x + threadIdx.x;
    if (idx >= (long)TT * 512) return;
    int t = (int)(idx >> 9);
    int i = (int)(idx & 511);
    float ex  = (2.0f * (float)i) / (float)KK;
    float inv = 1.0f / powf(10000.0f, ex);
    float th  = (float)t * inv;
    g_cos[idx] = cosf(th);
    g_sin[idx] = sinf(th);
}

__global__ void embed_ln_kernel(const int* __restrict__ input_,
                                const float* __restrict__ emb,
                                const float* __restrict__ pos) {
    int row = blockIdx.x;                 // B*T
    int t = row & (TT - 1);
    int tok = input_[row];
    float x = emb[(long)tok * DD + threadIdx.x];
    float mu = blockReduceSum256(x) * (1.0f / DD);
    float d = x - mu;
    float var = blockReduceSum256(d * d) * (1.0f / DD);
    float f = d * rsqrtf(var + EPS) + pos[(long)t * DD + threadIdx.x];
    g_v[(long)row * DD + threadIdx.x] = f;
    g_v2a[(long)row * DD + threadIdx.x] = __float2half_rn(f);
}

__global__ void combine_split_kernel(const float* __restrict__ pos, int do_pos) {
    long row = blockIdx.x;                 // B*T
    const long P = 4096L * 256;
    float u = g_yE[row * DD + threadIdx.x] + g_yE[P + row * DD + threadIdx.x] +
              g_yE[2 * P + row * DD + threadIdx.x] + g_yE[3 * P + row * DD + threadIdx.x];
    float mu = blockReduceSum256(u) * (1.0f / DD);
    float d = u - mu;
    float var = blockReduceSum256(d * d) * (1.0f / DD);
    float w = g_v[row * DD + threadIdx.x] + d * rsqrtf(var + EPS);
    float mu2 = blockReduceSum256(w) * (1.0f / DD);
    float d2 = w - mu2;
    float var2 = blockReduceSum256(d2 * d2) * (1.0f / DD);
    float f = d2 * rsqrtf(var2 + EPS);
    if (do_pos) {
        int t = (int)(row & (TT - 1));
        f += pos[(long)t * DD + threadIdx.x];
    }
    g_v[row * DD + threadIdx.x] = f;
    g_v2a[row * DD + threadIdx.x] = __float2half_rn(f);
}

__global__ void ln_split_kernel() {
    long row = blockIdx.x;                 // B*H*T
    float x = g_a[row * DD + threadIdx.x];
    float mu = blockReduceSum256(x) * (1.0f / DD);
    float d = x - mu;
    float var = blockReduceSum256(d * d) * (1.0f / DD);
    float f = d * rsqrtf(var + EPS);
    g_a2[row * DD + threadIdx.x] = __float2half_rn(f);
}

// wT = fp16(wP[0] + wP[1])   (2M elements)
__global__ void wsum_kernel() {
    const long N2 = 8L * 256 * 1024;
    long idx = (long)blockIdx.x * blockDim.x + threadIdx.x;
    if (idx >= N2) return;
    g_wT[idx] = __float2half_rn(g_wP[idx] + g_wP[idx + N2]);
}

// X [R,C] fp32 -> Y [C, R] fp16 hi
// PERM: 0 = none; 1 = permute OUT-ROW (X column) per 1024-block;
//       2 = permute OUT-COL (X row) per 1024-block.
__global__ void transpose_half_kernel(const float* __restrict__ X,
                                      __half* __restrict__ Y,
                                      int R, int C, long inZ, long outZ, int PERM) {
    __shared__ float tile[32][33];
    X += (long)blockIdx.z * inZ;
    Y += (long)blockIdx.z * outZ;
    int r0 = blockIdx.y * 32, c0 = blockIdx.x * 32;
    int tx = threadIdx.x, ty = threadIdx.y;   // (32,8)
    #pragma unroll
    for (int i = 0; i < 32; i += 8)
        tile[ty + i][tx] = X[(long)(r0 + ty + i) * C + c0 + tx];
    __syncthreads();
    #pragma unroll
    for (int i = 0; i < 32; i += 8) {
        float f = tile[tx][ty + i];           // X[r0+tx][c0+ty+i]
        int orowi = c0 + ty + i;
        int ocol  = r0 + tx;
        if (PERM == 1) {
            int blk = orowi & ~1023;
            orowi = blk + permk(orowi & 1023);
        } else if (PERM == 2) {
            int blk = ocol & ~1023;
            ocol = blk + permk(ocol & 1023);
        }
        Y[(long)orowi * R + ocol] = __float2half_rn(f);
    }
}

// ---------------- mma.sync GEMM (HMMA fp16 single-pass hi x hi) ----------------
// C[M,N] = Ah[M,K] x Bh[N,K]^T, fp32 accum.
// CTA tile 128x128, 3-stage cp.async pipeline (stage = 2 x 8192B = 16KB),
// XOR-swizzled 64B smem rows, single __syncthreads per chunk.
// 8 warps 2(m) x 4(n), warp tile 64x32.
// EPI: 0=fp32, 1=fp16 hi, 3=relu*G(fp16) -> fp16 hi,
//      4=relu + fused RoPE -> x gate fp16 [t,k] + qh [t,k] + qT [k,t]
// Split-K: nsplit partials, sp = blockIdx.z % nsplit.
#define OPER_BYTES 8192                    // 128 rows x 64B
#define STAGE_BYTES (2 * OPER_BYTES)       // 16384: Ah|Bh
#define SMEM_GEMM_BYTES (3 * STAGE_BYTES)  // 49152

template<int EPI>
__global__ void __launch_bounds__(256, 2)
gemm_mma(const __half* __restrict__ A, const __half* __restrict__ B,
         void* __restrict__ Cv, const __half* __restrict__ G,
         int Kd, int lda, int ldb, int ldc, int ldgt,
         long sAb, long sAh, long sBb, long sBh, long sCb, long sCh,
         long sGb, long sGh, int Hdim, int nsplit, long sSplitC,
         __half* __restrict__ Qh, __half* __restrict__ QT,
         const float* __restrict__ CT, const float* __restrict__ ST)
{
    extern __shared__ char dsm[];
    uint32_t sbase = smem_u32(dsm);

    int tid = threadIdx.x;
    int lane = tid & 31;
    int wid = tid >> 5;
    int wm = wid >> 2;        // 0..1
    int wn = wid & 3;         // 0..3

    int zz = blockIdx.z;
    int sp = 0, z = zz;
    if (nsplit > 1) { sp = zz % nsplit; z = zz / nsplit; }
    int bb = z / Hdim, hh = z - bb * Hdim;
    A += bb * sAb + hh * sAh;
    B += bb * sBb + hh * sBh;
    long cOff = bb * sCb + hh * sCh + sp * sSplitC;
    if (EPI == 3) G += bb * sGb + hh * sGh;
    long qhOff = 0, qtOff = 0;
    if (EPI == 4) {
        qhOff = (long)z * ((long)TT * KK);
        qtOff = (long)z * ((long)KK * TT);
    }

    int m0 = blockIdx.y * 128;
    int n0 = blockIdx.x * 128;

    const int KC = Kd >> 5;       // 32-wide chunks
    const int spK = sp * Kd;

    int lrow = tid >> 2;          // 0..63
    int lseg = tid & 3;

    auto issue = [&](int cc) {
        int koff = spK + (cc << 5);
        uint32_t st = sbase + (cc % 3) * STAGE_BYTES;
        #pragma unroll
        for (int i = 0; i < 2; i++) {
            uint32_t row = lrow + i * 64;
            uint32_t so = swz(row, (uint32_t)lseg);
            long go = lseg * 8;
            const __half* ga = A + (long)(m0 + row) * lda + koff + go;
            const __half* gb = B + (long)(n0 + row) * ldb + koff + go;
            CP_ASYNC16(st + so,              ga);
            CP_ASYNC16(st + OPER_BYTES + so, gb);
        }
    };

    float acc[4][4][4];
    #pragma unroll
    for (int i = 0; i < 4; i++)
        #pragma unroll
        for (int j = 0; j < 4; j++)
            #pragma unroll
            for (int r = 0; r < 4; r++) acc[i][j][r] = 0.0f;

    issue(0); CP_COMMIT();
    issue(1); CP_COMMIT();

    int rsel = lane & 15;
    int hi16 = lane >> 4;         // 0 or 1: second 16B seg of the k16 block

    for (int c = 0; c < KC; c++) {
        CP_WAIT1();              // chunk c data complete
        __syncthreads();         // copies visible; compute c-1 done

        uint32_t sah = sbase + (c % 3) * STAGE_BYTES;
        uint32_t sbh = sah + OPER_BYTES;

        #pragma unroll
        for (int ks = 0; ks < 2; ks++) {
            uint32_t segb = (uint32_t)(ks * 2 + hi16);
            uint32_t ar[4][4], br[2][4];
            #pragma unroll
            for (int n2 = 0; n2 < 2; n2++) {
                uint32_t row = (uint32_t)(wn * 32 + n2 * 16 + rsel);
                LDSM_X4(br[n2][0], br[n2][1], br[n2][2], br[n2][3], sbh + swz(row, segb));
            }
            #pragma unroll
            for (int mt = 0; mt < 4; mt++) {
                uint32_t row = (uint32_t)(wm * 64 + mt * 16 + rsel);
                LDSM_X4(ar[mt][0], ar[mt][1], ar[mt][2], ar[mt][3], sah + swz(row, segb));
            }
            #pragma unroll
            for (int mt = 0; mt < 4; mt++)
                #pragma unroll
                for (int nt = 0; nt < 4; nt++) {
                    int n2 = nt >> 1, j = nt & 1;
                    MMA16816(acc[mt][nt], ar[mt], br[n2][j], br[n2][2 + j]);
                }
            // hide next-chunk copy issue under the tensor-pipe shadow
            if (ks == 0) {
                if (c + 2 < KC) issue(c + 2);
                CP_COMMIT();
            }
        }
    }

    // ---------------- epilogue ----------------
    int g = lane >> 2, tg = lane & 3;
    float* Cf = (float*)Cv;
    __half* Cb = (__half*)Cv;

    #pragma unroll
    for (int mt = 0; mt < 4; mt++) {
        #pragma unroll
        for (int half = 0; half < 2; half++) {
            long row = m0 + wm * 64 + mt * 16 + g + half * 8;
            #pragma unroll
            for (int nt = 0; nt < 4; nt++) {
                int co = n0 + wn * 32 + nt * 8 + tg * 2;
                float f0 = acc[mt][nt][half * 2 + 0];
                float f1 = acc[mt][nt][half * 2 + 1];
                if (EPI == 0) {
                    *reinterpret_cast<float2*>(&Cf[cOff + row * ldc + co]) =
                        make_float2(f0, f1);
                } else if (EPI == 1) {
                    *reinterpret_cast<uint32_t*>(&Cb[cOff + row * ldc + co]) =
                        pack2(__float2half_rn(f0), __float2half_rn(f1));
                } else if (EPI == 4) {
                    f0 = fmaxf(f0, 0.f);
                    f1 = fmaxf(f1, 0.f);
                    // gate x in fp16 (permuted cols)
                    *reinterpret_cast<uint32_t*>(&Cb[cOff + row * ldc + co]) =
                        pack2(__float2half_rn(f0), __float2half_rn(f1));
                    // RoPE: pair (co, co+1) = original (i, i+512), i = co/2
                    int i = co >> 1;
                    long tb = row * 512 + i;   // row == t
                    float cv = CT[tb], sv = ST[tb];
                    float qa = f0 * cv - f1 * sv;
                    float qb = f1 * cv + f0 * sv;
                    __half h0 = __float2half_rn(qa);
                    __half h1 = __float2half_rn(qb);
                    *reinterpret_cast<uint32_t*>(&Qh[qhOff + row * KK + co]) = pack2(h0, h1);
                    __half* qt = QT + qtOff + (long)co * TT + row;
                    qt[0]  = h0;
                    qt[TT] = h1;
                } else {  // EPI == 3
                    __half2 gv = *reinterpret_cast<const __half2*>(
                        &G[row * (long)ldgt + co]);
                    f0 = fmaxf(f0, 0.f) * __half2float(__low2half(gv));
                    f1 = fmaxf(f1, 0.f) * __half2float(__high2half(gv));
                    *reinterpret_cast<uint32_t*>(&Cb[cOff + row * ldc + co]) =
                        pack2(__float2half_rn(f0), __float2half_rn(f1));
                }
            }
        }
    }
}

// ---------------- host launch ----------------
extern "C" void kernel_launch(void* const* d_in, const int* in_sizes, int n_in,
                              void* d_out, int out_size) {
    const int*   input_  = (const int*)d_in[0];
    const float* emb     = (const float*)d_in[1];
    const float* pos     = (const float*)d_in[2];
    const float* Dx      = (const float*)d_in[3];
    const float* Dy      = (const float*)d_in[4];
    const float* E       = (const float*)d_in[5];
    const float* readout = (const float*)d_in[6];
    float* out = (float*)d_out;

    cudaFuncSetAttribute(gemm_mma<0>, cudaFuncAttributeMaxDynamicSharedMemorySize, SMEM_GEMM_BYTES);
    cudaFuncSetAttribute(gemm_mma<1>, cudaFuncAttributeMaxDynamicSharedMemorySize, SMEM_GEMM_BYTES);
    cudaFuncSetAttribute(gemm_mma<3>, cudaFuncAttributeMaxDynamicSharedMemorySize, SMEM_GEMM_BYTES);
    cudaFuncSetAttribute(gemm_mma<4>, cudaFuncAttributeMaxDynamicSharedMemorySize, SMEM_GEMM_BYTES);

    float *v, *a, *yE, *ct, *st, *wP;
    __half *v2a, *vT, *x, *qh, *qT, *wT, *a2, *y2, *Dx2, *Dy2, *E2, *ro2;
    cudaGetSymbolAddress((void**)&v,   g_v);
    cudaGetSymbolAddress((void**)&v2a, g_v2a);
    cudaGetSymbolAddress((void**)&vT,  g_vT);
    cudaGetSymbolAddress((void**)&x,   g_x);
    cudaGetSymbolAddress((void**)&qh,  g_qh);
    cudaGetSymbolAddress((void**)&qT,  g_qT);
    cudaGetSymbolAddress((void**)&wP,  g_wP);
    cudaGetSymbolAddress((void**)&wT,  g_wT);
    cudaGetSymbolAddress((void**)&a,   g_a);
    cudaGetSymbolAddress((void**)&a2,  g_a2);
    cudaGetSymbolAddress((void**)&y2,  g_y2);
    cudaGetSymbolAddress((void**)&yE,  g_yE);
    cudaGetSymbolAddress((void**)&Dx2, g_Dx2);
    cudaGetSymbolAddress((void**)&Dy2, g_Dy2);
    cudaGetSymbolAddress((void**)&E2,  g_E2);
    cudaGetSymbolAddress((void**)&ro2, g_ro2);
    cudaGetSymbolAddress((void**)&ct,  g_cos);
    cudaGetSymbolAddress((void**)&st,  g_sin);

    dim3 tb(32, 8);

    rope_table_kernel<<<(TT * 512 + 255) / 256, 256>>>();
    embed_ln_kernel<<<BB * TT, 256>>>(input_, emb, pos);
    transpose_half_kernel<<<dim3(KK / 32, DD / 32, HH), tb>>>(Dx, Dx2, DD, KK, (long)DD * KK, (long)KK * DD, 1);
    transpose_half_kernel<<<dim3(KK / 32, DD / 32, HH), tb>>>(Dy, Dy2, DD, KK, (long)DD * KK, (long)KK * DD, 1);
    transpose_half_kernel<<<dim3(DD / 32, NN_ / 32, 1), tb>>>(E, E2, NN_, DD, 0, 0, 2);
    transpose_half_kernel<<<dim3(BV / 32, DD / 32, 1), tb>>>(readout, ro2, DD, BV, 0, 0, 0);

    const long TK  = (long)TT * KK;
    const long TD  = (long)TT * DD;
    const long TN  = (long)TT * NN_;
    const long QTS = (long)KK * TT;        // qT per-bh stride
    const long WTS = (long)DD * KK;        // wT/wP per-bh stride

    for (int l = 0; l < LL; l++) {
        transpose_half_kernel<<<dim3(DD / 32, TT / 32, BB), tb>>>(v, vT, TT, DD, TD, (long)DD * TT, 0);

        // x = relu(v2a @ Dx2^T) fp16 gate (permuted) + RoPE -> qh [t,k], qT [k,t]
        gemm_mma<4><<<dim3(KK / 128, TT / 128, BB * HH), 256, SMEM_GEMM_BYTES>>>(
            v2a, Dx2, x, nullptr,
            DD, DD, DD, KK, 0,
            TD, 0, 0, (long)KK * DD, (long)HH * TK, TK, 0, 0, HH, 1, 0,
            qh, qT, ct, st);

        // wP[sp] = vT @ qT^T (split-K=2, fp32 partials) : M=256 N=1024 Kc=1024/split
        gemm_mma<0><<<dim3(KK / 128, DD / 128, BB * HH * 2), 256, SMEM_GEMM_BYTES>>>(
            vT, qT, wP, nullptr,
            TT / 2, TT, TT, KK, 0,
            (long)DD * TT, 0, (long)HH * QTS, QTS, (long)HH * WTS, WTS, 0, 0, HH, 2, 8L * 256 * 1024,
            nullptr, nullptr, nullptr, nullptr);

        // wT = fp16(wP[0] + wP[1])
        wsum_kernel<<<(int)((8L * 256 * 1024 + 255) / 256), 256>>>();

        // a[b,h] = qh @ wT^T fp32 : M=2048(t) N=256(d) Kc=1024(k)
        gemm_mma<0><<<dim3(DD / 128, TT / 128, BB * HH), 256, SMEM_GEMM_BYTES>>>(
            qh, wT, a, nullptr,
            KK, KK, KK, DD, 0,
            (long)HH * TK, TK, (long)HH * WTS, WTS, (long)HH * TD, TD, 0, 0, HH, 1, 0,
            nullptr, nullptr, nullptr, nullptr);

        ln_split_kernel<<<BB * HH * TT, 256>>>();

        // y2[b,t,h*K+n'] = relu(a2 @ Dy2^T) * x (fp16 gate, permuted cols)
        gemm_mma<3><<<dim3(KK / 128, TT / 128, BB * HH), 256, SMEM_GEMM_BYTES>>>(
            a2, Dy2, y2, x,
            DD, DD, DD, NN_, KK,
            (long)HH * TD, TD, 0, (long)KK * DD,
            TN, (long)KK, (long)HH * TK, TK, HH, 1, 0,
            nullptr, nullptr, nullptr, nullptr);

        // yE partials = y2 @ E2^T (split-K=4) : M=4096 N=256
        gemm_mma<0><<<dim3(DD / 128, (BB * TT) / 128, 4), 256, SMEM_GEMM_BYTES>>>(
            y2, E2, yE, nullptr,
            NN_ / 4, NN_, NN_, DD, 0,
            0, 0, 0, 0, 0, 0, 0, 0, 1, 4, 4096L * 256,
            nullptr, nullptr, nullptr, nullptr);

        combine_split_kernel<<<BB * TT, 256>>>(pos, l < LL - 1 ? 1 : 0);
    }

    // out = v2a @ ro2^T fp32 : M=4096 N=32000 Kd=256
    gemm_mma<0><<<dim3(BV / 128, (BB * TT) / 128, 1), 256, SMEM_GEMM_BYTES>>>(
        v2a, ro2, out, nullptr,
        DD, DD, DD, BV, 0,
        0, 0, 0, 0, 0, 0, 0, 0, 1, 1, 0,
        nullptr, nullptr, nullptr, nullptr);
}